// round 1
// baseline (speedup 1.0000x reference)
#include <cuda_runtime.h>
#include <math.h>

// Problem constants
#define B_   2
#define S_   2048
#define H_   2048
#define NH_  16
#define HD_  128
#define NE_  8
#define I_   4096
#define T_   (B_*S_)          // 4096 tokens
#define EPS_ 1e-5f
#define ATT_SCALE 0.08838834764831845f   // 1/sqrt(128)

// -------------------- scratch (device globals; no allocation) --------------------
__device__ float g_xn [(size_t)T_*H_];
__device__ float g_q  [(size_t)T_*H_];
__device__ float g_k  [(size_t)T_*H_];
__device__ float g_v  [(size_t)T_*H_];
__device__ float g_att[(size_t)B_*NH_*S_*S_];   // 537 MB materialized attention
__device__ float g_ao [(size_t)T_*H_];
__device__ float g_xn2[(size_t)T_*H_];
__device__ float g_hg [(size_t)T_*I_];
__device__ float g_hu [(size_t)T_*I_];
__device__ int   g_tok[NE_*T_];
__device__ float g_wt [NE_*T_];
__device__ int   g_cnt[NE_];

// -------------------- small kernels --------------------
__global__ void zero_cnt_k() {
    if (threadIdx.x < NE_) g_cnt[threadIdx.x] = 0;
}

__global__ void rmsnorm_k(const float* __restrict__ x, const float* __restrict__ w,
                          float* __restrict__ o) {
    int t = blockIdx.x;
    const float* xr = x + (size_t)t * H_;
    float s = 0.f;
    for (int j = threadIdx.x; j < H_; j += blockDim.x) { float v = xr[j]; s += v * v; }
    __shared__ float red[32];
    for (int off = 16; off; off >>= 1) s += __shfl_xor_sync(0xffffffffu, s, off);
    if ((threadIdx.x & 31) == 0) red[threadIdx.x >> 5] = s;
    __syncthreads();
    if (threadIdx.x < 32) {
        float v = (threadIdx.x < (blockDim.x >> 5)) ? red[threadIdx.x] : 0.f;
        for (int off = 16; off; off >>= 1) v += __shfl_xor_sync(0xffffffffu, v, off);
        if (threadIdx.x == 0) red[0] = v;
    }
    __syncthreads();
    float inv = rsqrtf(red[0] / (float)H_ + EPS_);
    float* orow = o + (size_t)t * H_;
    for (int j = threadIdx.x; j < H_; j += blockDim.x) orow[j] = xr[j] * inv * w[j];
}

__global__ void add_residual_k(float* __restrict__ y, const float* __restrict__ x) {
    size_t i = (size_t)blockIdx.x * blockDim.x + threadIdx.x;
    if (i < (size_t)T_ * H_) y[i] += x[i];
}

__global__ void swiglu_k(float* __restrict__ hg, const float* __restrict__ hu) {
    int cnt = g_cnt[blockIdx.y];   // unused dim trick avoided: pass via grid? simpler below
}

// real swiglu: count passed via device pointer
__global__ void swiglu2_k(float* __restrict__ hg, const float* __restrict__ hu,
                          const int* __restrict__ cntp) {
    int cnt = *cntp;
    size_t total = (size_t)cnt * I_;
    size_t stride = (size_t)gridDim.x * blockDim.x;
    for (size_t i = (size_t)blockIdx.x * blockDim.x + threadIdx.x; i < total; i += stride) {
        float g = hg[i], u = hu[i];
        hg[i] = (g / (1.f + expf(-g))) * u;
    }
}

// -------------------- generic tiled SGEMM: C[M,N] = A[M,K] * B[N,K]^T --------------------
// Optional: a_idx (gather rows of A), cnt_ptr (effective M), c_idx/c_w (scatter-add epilogue)
__global__ void __launch_bounds__(256, 2)
gemm_bt_k(const float* __restrict__ A, const float* __restrict__ B, float* __restrict__ C,
          int M, int N, int K, int lda, int ldb, int ldc,
          const int* __restrict__ a_idx, const int* __restrict__ cnt_ptr,
          const int* __restrict__ c_idx, const float* __restrict__ c_w) {
    int cnt = cnt_ptr ? *cnt_ptr : M;
    int m0 = blockIdx.y * 128, n0 = blockIdx.x * 128;
    if (m0 >= cnt) return;

    __shared__ float As[8][128];
    __shared__ float Bs[8][128];
    int tid = threadIdx.x;
    int tx = tid & 15, ty = tid >> 4;

    int lm = tid >> 1;            // 0..127
    int lk = (tid & 1) * 4;       // 0 or 4
    int arow = m0 + lm;
    const float* Abase = nullptr;
    if (arow < cnt) {
        int grow = a_idx ? a_idx[arow] : arow;
        Abase = A + (size_t)grow * lda;
    }
    const float* Bbase = B + (size_t)(n0 + lm) * ldb;

    float acc[8][8];
#pragma unroll
    for (int i = 0; i < 8; i++)
#pragma unroll
        for (int j = 0; j < 8; j++) acc[i][j] = 0.f;

    for (int kb = 0; kb < K; kb += 8) {
        float4 av = make_float4(0.f, 0.f, 0.f, 0.f);
        if (Abase) av = *(const float4*)(Abase + kb + lk);
        float4 bv = *(const float4*)(Bbase + kb + lk);
        As[lk + 0][lm] = av.x; As[lk + 1][lm] = av.y;
        As[lk + 2][lm] = av.z; As[lk + 3][lm] = av.w;
        Bs[lk + 0][lm] = bv.x; Bs[lk + 1][lm] = bv.y;
        Bs[lk + 2][lm] = bv.z; Bs[lk + 3][lm] = bv.w;
        __syncthreads();
#pragma unroll
        for (int kk = 0; kk < 8; kk++) {
            float a[8], b[8];
#pragma unroll
            for (int i = 0; i < 8; i++) a[i] = As[kk][ty * 8 + i];
#pragma unroll
            for (int j = 0; j < 8; j++) b[j] = Bs[kk][tx * 8 + j];
#pragma unroll
            for (int i = 0; i < 8; i++)
#pragma unroll
                for (int j = 0; j < 8; j++) acc[i][j] += a[i] * b[j];
        }
        __syncthreads();
    }

    if (c_idx) {
#pragma unroll
        for (int i = 0; i < 8; i++) {
            int m = m0 + ty * 8 + i;
            if (m >= cnt) continue;
            int tr = c_idx[m]; float wv = c_w[m];
            float* crow = C + (size_t)tr * ldc + n0 + tx * 8;
#pragma unroll
            for (int j = 0; j < 8; j++) crow[j] += wv * acc[i][j];
        }
    } else {
#pragma unroll
        for (int i = 0; i < 8; i++) {
            int m = m0 + ty * 8 + i;
            if (m >= cnt) continue;
            float* crow = C + (size_t)m * ldc + n0 + tx * 8;
#pragma unroll
            for (int j = 0; j < 8; j++) crow[j] = acc[i][j];
        }
    }
}

// -------------------- causal attention scores: S = scale * Q K^T, masked --------------------
__global__ void __launch_bounds__(256, 2)
attn_score_k(const float* __restrict__ Q, const float* __restrict__ Km) {
    int bh = blockIdx.z;
    int b = bh >> 4, h = bh & 15;
    int m0 = blockIdx.y * 128, n0 = blockIdx.x * 128;
    float* Srow = g_att + (size_t)bh * S_ * S_;
    int tid = threadIdx.x, tx = tid & 15, ty = tid >> 4;

    if (n0 > m0 + 127) {   // fully masked tile
#pragma unroll
        for (int i = 0; i < 8; i++) {
            float* crow = Srow + (size_t)(m0 + ty * 8 + i) * S_ + n0 + tx * 8;
#pragma unroll
            for (int j = 0; j < 8; j++) crow[j] = -1e30f;
        }
        return;
    }

    const float* Qb = Q + (size_t)b * S_ * H_ + h * HD_;
    const float* Kb = Km + (size_t)b * S_ * H_ + h * HD_;
    __shared__ float As[8][128];
    __shared__ float Bs[8][128];
    int lm = tid >> 1, lk = (tid & 1) * 4;
    const float* Abase = Qb + (size_t)(m0 + lm) * H_;
    const float* Bbase = Kb + (size_t)(n0 + lm) * H_;

    float acc[8][8];
#pragma unroll
    for (int i = 0; i < 8; i++)
#pragma unroll
        for (int j = 0; j < 8; j++) acc[i][j] = 0.f;

    for (int kb = 0; kb < HD_; kb += 8) {
        float4 av = *(const float4*)(Abase + kb + lk);
        float4 bv = *(const float4*)(Bbase + kb + lk);
        As[lk + 0][lm] = av.x; As[lk + 1][lm] = av.y;
        As[lk + 2][lm] = av.z; As[lk + 3][lm] = av.w;
        Bs[lk + 0][lm] = bv.x; Bs[lk + 1][lm] = bv.y;
        Bs[lk + 2][lm] = bv.z; Bs[lk + 3][lm] = bv.w;
        __syncthreads();
#pragma unroll
        for (int kk = 0; kk < 8; kk++) {
            float a[8], b2[8];
#pragma unroll
            for (int i = 0; i < 8; i++) a[i] = As[kk][ty * 8 + i];
#pragma unroll
            for (int j = 0; j < 8; j++) b2[j] = Bs[kk][tx * 8 + j];
#pragma unroll
            for (int i = 0; i < 8; i++)
#pragma unroll
                for (int j = 0; j < 8; j++) acc[i][j] += a[i] * b2[j];
        }
        __syncthreads();
    }

#pragma unroll
    for (int i = 0; i < 8; i++) {
        int row = m0 + ty * 8 + i;
        float* crow = Srow + (size_t)row * S_ + n0 + tx * 8;
#pragma unroll
        for (int j = 0; j < 8; j++) {
            int col = n0 + tx * 8 + j;
            crow[j] = (col > row) ? -1e30f : acc[i][j] * ATT_SCALE;
        }
    }
}

// -------------------- row softmax over g_att --------------------
__global__ void softmax_k() {
    float* row = g_att + (size_t)blockIdx.x * S_;
    float v[8];
#pragma unroll
    for (int i = 0; i < 8; i++) v[i] = row[threadIdx.x + i * 256];
    float mx = v[0];
#pragma unroll
    for (int i = 1; i < 8; i++) mx = fmaxf(mx, v[i]);
    __shared__ float red[32];
    for (int off = 16; off; off >>= 1) mx = fmaxf(mx, __shfl_xor_sync(0xffffffffu, mx, off));
    if ((threadIdx.x & 31) == 0) red[threadIdx.x >> 5] = mx;
    __syncthreads();
    if (threadIdx.x < 32) {
        float m2 = (threadIdx.x < 8) ? red[threadIdx.x] : -1e38f;
        for (int off = 16; off; off >>= 1) m2 = fmaxf(m2, __shfl_xor_sync(0xffffffffu, m2, off));
        if (threadIdx.x == 0) red[0] = m2;
    }
    __syncthreads();
    mx = red[0];
    float s = 0.f;
#pragma unroll
    for (int i = 0; i < 8; i++) { v[i] = expf(v[i] - mx); s += v[i]; }
    __syncthreads();
    for (int off = 16; off; off >>= 1) s += __shfl_xor_sync(0xffffffffu, s, off);
    if ((threadIdx.x & 31) == 0) red[threadIdx.x >> 5] = s;
    __syncthreads();
    if (threadIdx.x < 32) {
        float s2 = (threadIdx.x < 8) ? red[threadIdx.x] : 0.f;
        for (int off = 16; off; off >>= 1) s2 += __shfl_xor_sync(0xffffffffu, s2, off);
        if (threadIdx.x == 0) red[0] = s2;
    }
    __syncthreads();
    float inv = 1.f / red[0];
#pragma unroll
    for (int i = 0; i < 8; i++) row[threadIdx.x + i * 256] = v[i] * inv;
}

// -------------------- P @ V (causal-truncated K loop) --------------------
__global__ void __launch_bounds__(256, 2)
attn_pv_k(const float* __restrict__ V) {
    int bh = blockIdx.z;
    int b = bh >> 4, h = bh & 15;
    int m0 = blockIdx.x * 128;
    const float* Pb = g_att + (size_t)bh * S_ * S_;
    const float* Vb = V + (size_t)b * S_ * H_ + h * HD_;
    float* Ob = g_ao + (size_t)b * S_ * H_ + h * HD_;

    __shared__ float As[8][128];
    __shared__ float Bs[8][128];
    int tid = threadIdx.x, tx = tid & 15, ty = tid >> 4;
    int lm = tid >> 1, lk = (tid & 1) * 4;
    int bk = tid >> 5, bn = (tid & 31) * 4;

    float acc[8][8];
#pragma unroll
    for (int i = 0; i < 8; i++)
#pragma unroll
        for (int j = 0; j < 8; j++) acc[i][j] = 0.f;

    int kmax = m0 + 128;   // P[m, j] == 0 for j > m (row max in tile = m0+127)
    for (int kb = 0; kb < kmax; kb += 8) {
        float4 av = *(const float4*)(Pb + (size_t)(m0 + lm) * S_ + kb + lk);
        As[lk + 0][lm] = av.x; As[lk + 1][lm] = av.y;
        As[lk + 2][lm] = av.z; As[lk + 3][lm] = av.w;
        float4 bv = *(const float4*)(Vb + (size_t)(kb + bk) * H_ + bn);
        Bs[bk][bn + 0] = bv.x; Bs[bk][bn + 1] = bv.y;
        Bs[bk][bn + 2] = bv.z; Bs[bk][bn + 3] = bv.w;
        __syncthreads();
#pragma unroll
        for (int kk = 0; kk < 8; kk++) {
            float a[8], b2[8];
#pragma unroll
            for (int i = 0; i < 8; i++) a[i] = As[kk][ty * 8 + i];
#pragma unroll
            for (int j = 0; j < 8; j++) b2[j] = Bs[kk][tx * 8 + j];
#pragma unroll
            for (int i = 0; i < 8; i++)
#pragma unroll
                for (int j = 0; j < 8; j++) acc[i][j] += a[i] * b2[j];
        }
        __syncthreads();
    }

#pragma unroll
    for (int i = 0; i < 8; i++) {
        float* crow = Ob + (size_t)(m0 + ty * 8 + i) * H_ + tx * 8;
#pragma unroll
        for (int j = 0; j < 8; j++) crow[j] = acc[i][j];
    }
}

// -------------------- router: top-2, softmax weights, build expert lists --------------------
__global__ void router_k(const float* __restrict__ xn2, const float* __restrict__ Wr) {
    int t = blockIdx.x * (blockDim.x >> 5) + (threadIdx.x >> 5);
    if (t >= T_) return;
    int lane = threadIdx.x & 31;
    const float* xr = xn2 + (size_t)t * H_;
    float s[NE_];
#pragma unroll
    for (int e = 0; e < NE_; e++) s[e] = 0.f;
    for (int j = lane; j < H_; j += 32) {
        float xv = xr[j];
#pragma unroll
        for (int e = 0; e < NE_; e++) s[e] += xv * Wr[e * H_ + j];
    }
#pragma unroll
    for (int e = 0; e < NE_; e++)
        for (int off = 16; off; off >>= 1) s[e] += __shfl_xor_sync(0xffffffffu, s[e], off);
    if (lane == 0) {
        int b0 = 0;
#pragma unroll
        for (int e = 1; e < NE_; e++) if (s[e] > s[b0]) b0 = e;
        int b1 = -1;
#pragma unroll
        for (int e = 0; e < NE_; e++) {
            if (e == b0) continue;
            if (b1 < 0 || s[e] > s[b1]) b1 = e;
        }
        float m = s[b0];
        float e0 = expf(s[b0] - m), e1 = expf(s[b1] - m);
        float inv = 1.f / (e0 + e1);
        int pos = atomicAdd(&g_cnt[b0], 1);
        g_tok[b0 * T_ + pos] = t; g_wt[b0 * T_ + pos] = e0 * inv;
        pos = atomicAdd(&g_cnt[b1], 1);
        g_tok[b1 * T_ + pos] = t; g_wt[b1 * T_ + pos] = e1 * inv;
    }
}

// -------------------- host --------------------
extern "C" void kernel_launch(void* const* d_in, const int* in_sizes, int n_in,
                              void* d_out, int out_size) {
    const float* x    = (const float*)d_in[0];
    const float* Wq   = (const float*)d_in[1];
    const float* Wk   = (const float*)d_in[2];
    const float* Wv   = (const float*)d_in[3];
    const float* Wo   = (const float*)d_in[4];
    const float* wln1 = (const float*)d_in[5];
    const float* wln2 = (const float*)d_in[6];
    const float* Wr   = (const float*)d_in[7];
    const float* Wg   = (const float*)d_in[8];
    const float* Wu   = (const float*)d_in[9];
    const float* Wd   = (const float*)d_in[10];
    float* out = (float*)d_out;

    float *p_xn, *p_q, *p_k, *p_v, *p_ao, *p_xn2, *p_hg, *p_hu, *p_wt;
    int *p_tok, *p_cnt;
    cudaGetSymbolAddress((void**)&p_xn,  g_xn);
    cudaGetSymbolAddress((void**)&p_q,   g_q);
    cudaGetSymbolAddress((void**)&p_k,   g_k);
    cudaGetSymbolAddress((void**)&p_v,   g_v);
    cudaGetSymbolAddress((void**)&p_ao,  g_ao);
    cudaGetSymbolAddress((void**)&p_xn2, g_xn2);
    cudaGetSymbolAddress((void**)&p_hg,  g_hg);
    cudaGetSymbolAddress((void**)&p_hu,  g_hu);
    cudaGetSymbolAddress((void**)&p_tok, g_tok);
    cudaGetSymbolAddress((void**)&p_wt,  g_wt);
    cudaGetSymbolAddress((void**)&p_cnt, g_cnt);

    zero_cnt_k<<<1, 32>>>();

    // 1. rmsnorm 1
    rmsnorm_k<<<T_, 256>>>(x, wln1, p_xn);

    // 2. QKV projections
    dim3 gProj(H_ / 128, T_ / 128);
    gemm_bt_k<<<gProj, 256>>>(p_xn, Wq, p_q, T_, H_, H_, H_, H_, H_,
                              nullptr, nullptr, nullptr, nullptr);
    gemm_bt_k<<<gProj, 256>>>(p_xn, Wk, p_k, T_, H_, H_, H_, H_, H_,
                              nullptr, nullptr, nullptr, nullptr);
    gemm_bt_k<<<gProj, 256>>>(p_xn, Wv, p_v, T_, H_, H_, H_, H_, H_,
                              nullptr, nullptr, nullptr, nullptr);

    // 3. attention
    attn_score_k<<<dim3(S_ / 128, S_ / 128, B_ * NH_), 256>>>(p_q, p_k);
    softmax_k<<<B_ * NH_ * S_, 256>>>();
    attn_pv_k<<<dim3(S_ / 128, 1, B_ * NH_), 256>>>(p_v);

    // 4. output projection + residual
    gemm_bt_k<<<gProj, 256>>>(p_ao, Wo, out, T_, H_, H_, H_, H_, H_,
                              nullptr, nullptr, nullptr, nullptr);
    add_residual_k<<<(T_ * H_) / 256, 256>>>(out, x);

    // 5. rmsnorm 2
    rmsnorm_k<<<T_, 256>>>(out, wln2, p_xn2);

    // 6. router
    router_k<<<T_ / 8, 256>>>(p_xn2, Wr);

    // 7. experts
    for (int e = 0; e < NE_; e++) {
        const float* Wge = Wg + (size_t)e * I_ * H_;
        const float* Wue = Wu + (size_t)e * I_ * H_;
        const float* Wde = Wd + (size_t)e * H_ * I_;
        const int*   tok = p_tok + e * T_;
        const float* wte = p_wt + e * T_;
        const int*   cnt = p_cnt + e;
        dim3 gUp(I_ / 128, T_ / 128);
        gemm_bt_k<<<gUp, 256>>>(p_xn2, Wge, p_hg, T_, I_, H_, H_, H_, I_,
                                tok, cnt, nullptr, nullptr);
        gemm_bt_k<<<gUp, 256>>>(p_xn2, Wue, p_hu, T_, I_, H_, H_, H_, I_,
                                tok, cnt, nullptr, nullptr);
        swiglu2_k<<<2048, 256>>>(p_hg, p_hu, cnt);
        dim3 gDn(H_ / 128, T_ / 128);
        gemm_bt_k<<<gDn, 256>>>(p_hg, Wde, out, T_, H_, I_, I_, I_, H_,
                                nullptr, cnt, tok, wte);
    }
}

// round 2
// speedup vs baseline: 2.6199x; 2.6199x over previous
#include <cuda_runtime.h>
#include <math.h>
#include <stdint.h>

#define B_   2
#define S_   2048
#define H_   2048
#define NH_  16
#define HD_  128
#define NE_  8
#define I_   4096
#define T_   (B_*S_)
#define EPS_ 1e-5f
#define ATT_SCALE 0.08838834764831845f

// -------------------- scratch --------------------
__device__ float g_xn [(size_t)T_*H_];
__device__ float g_q  [(size_t)T_*H_];
__device__ float g_k  [(size_t)T_*H_];
__device__ float g_v  [(size_t)T_*H_];
__device__ float g_att[(size_t)B_*NH_*S_*S_];
__device__ float g_ao [(size_t)T_*H_];
__device__ float g_xn2[(size_t)T_*H_];
__device__ float g_hg [(size_t)T_*I_];
__device__ float g_hu [(size_t)T_*I_];
__device__ int   g_tok[NE_*T_];
__device__ float g_wt [NE_*T_];
__device__ int   g_cnt[NE_];

// -------------------- helpers --------------------
__device__ __forceinline__ uint32_t f2tf(float f) {
    uint32_t r; asm("cvt.rna.tf32.f32 %0, %1;" : "=r"(r) : "f"(f)); return r;
}
__device__ __forceinline__ void mma8(float* c, const uint32_t* a, uint32_t b0, uint32_t b1) {
    asm volatile("mma.sync.aligned.m16n8k8.row.col.f32.tf32.tf32.f32 "
        "{%0,%1,%2,%3},{%4,%5,%6,%7},{%8,%9},{%0,%1,%2,%3};"
        : "+f"(c[0]), "+f"(c[1]), "+f"(c[2]), "+f"(c[3])
        : "r"(a[0]), "r"(a[1]), "r"(a[2]), "r"(a[3]), "r"(b0), "r"(b1));
}

// -------------------- small kernels --------------------
__global__ void zero_cnt_k() { if (threadIdx.x < NE_) g_cnt[threadIdx.x] = 0; }

__global__ void rmsnorm_k(const float* __restrict__ x, const float* __restrict__ w,
                          float* __restrict__ o) {
    int t = blockIdx.x;
    const float* xr = x + (size_t)t * H_;
    float s = 0.f;
    for (int j = threadIdx.x; j < H_; j += blockDim.x) { float v = xr[j]; s += v * v; }
    __shared__ float red[32];
    for (int off = 16; off; off >>= 1) s += __shfl_xor_sync(0xffffffffu, s, off);
    if ((threadIdx.x & 31) == 0) red[threadIdx.x >> 5] = s;
    __syncthreads();
    if (threadIdx.x < 32) {
        float v = (threadIdx.x < (blockDim.x >> 5)) ? red[threadIdx.x] : 0.f;
        for (int off = 16; off; off >>= 1) v += __shfl_xor_sync(0xffffffffu, v, off);
        if (threadIdx.x == 0) red[0] = v;
    }
    __syncthreads();
    float inv = rsqrtf(red[0] / (float)H_ + EPS_);
    float* orow = o + (size_t)t * H_;
    for (int j = threadIdx.x; j < H_; j += blockDim.x) orow[j] = xr[j] * inv * w[j];
}

__global__ void add_residual_k(float* __restrict__ y, const float* __restrict__ x) {
    size_t i = (size_t)blockIdx.x * blockDim.x + threadIdx.x;
    float4* Y = (float4*)y; const float4* X = (const float4*)x;
    if (i < (size_t)T_ * H_ / 4) {
        float4 a = Y[i], b = X[i];
        a.x += b.x; a.y += b.y; a.z += b.z; a.w += b.w;
        Y[i] = a;
    }
}

__global__ void swiglu2_k(float* __restrict__ hg, const float* __restrict__ hu,
                          const int* __restrict__ cntp) {
    int cnt = *cntp;
    size_t total = (size_t)cnt * (I_ / 4);
    size_t stride = (size_t)gridDim.x * blockDim.x;
    float4* G = (float4*)hg; const float4* U = (const float4*)hu;
    for (size_t i = (size_t)blockIdx.x * blockDim.x + threadIdx.x; i < total; i += stride) {
        float4 g = G[i], u = U[i];
        g.x = g.x / (1.f + __expf(-g.x)) * u.x;
        g.y = g.y / (1.f + __expf(-g.y)) * u.y;
        g.z = g.z / (1.f + __expf(-g.z)) * u.z;
        g.w = g.w / (1.f + __expf(-g.w)) * u.w;
        G[i] = g;
    }
}

// ==================== tf32 MMA GEMM: C[M,N] = A[M,K] * B[N,K]^T ====================
// Optional row gather (a_idx), dynamic M (cnt_ptr), scatter-add epilogue (c_idx/c_w).
__global__ void __launch_bounds__(256)
mma_gemm_bt(const float* __restrict__ A, const float* __restrict__ B, float* __restrict__ C,
            int M, int N, int K, int lda, int ldb, int ldc,
            const int* __restrict__ a_idx, const int* __restrict__ cnt_ptr,
            const int* __restrict__ c_idx, const float* __restrict__ c_w) {
    int cnt = cnt_ptr ? *cnt_ptr : M;
    int m0 = blockIdx.y * 128, n0 = blockIdx.x * 128;
    if (m0 >= cnt) return;

    __shared__ uint32_t As[128][20];
    __shared__ uint32_t Bs[128][20];

    int tid = threadIdx.x;
    int lane = tid & 31, w = tid >> 5;
    int wm = (w & 3) * 32, wn = (w >> 2) * 64;
    int r1 = tid >> 2;
    int c4 = (tid & 3) * 4;

    const float* aP[2];
    {
        int mr0 = m0 + r1, mr1 = m0 + r1 + 64;
        int g0 = (mr0 < cnt) ? (a_idx ? a_idx[mr0] : mr0) : 0;
        int g1 = (mr1 < cnt) ? (a_idx ? a_idx[mr1] : mr1) : 0;
        aP[0] = A + (size_t)g0 * lda + c4;
        aP[1] = A + (size_t)g1 * lda + c4;
    }
    const float* bP[2] = { B + (size_t)(n0 + r1) * ldb + c4,
                           B + (size_t)(n0 + r1 + 64) * ldb + c4 };

    float acc[2][8][4];
#pragma unroll
    for (int i = 0; i < 2; i++)
#pragma unroll
        for (int j = 0; j < 8; j++)
#pragma unroll
            for (int q = 0; q < 4; q++) acc[i][j][q] = 0.f;

    for (int kb = 0; kb < K; kb += 16) {
#pragma unroll
        for (int h = 0; h < 2; h++) {
            float4 av = *(const float4*)(aP[h] + kb);
            float4 bv = *(const float4*)(bP[h] + kb);
            int rr = r1 + h * 64;
            As[rr][c4 + 0] = f2tf(av.x); As[rr][c4 + 1] = f2tf(av.y);
            As[rr][c4 + 2] = f2tf(av.z); As[rr][c4 + 3] = f2tf(av.w);
            Bs[rr][c4 + 0] = f2tf(bv.x); Bs[rr][c4 + 1] = f2tf(bv.y);
            Bs[rr][c4 + 2] = f2tf(bv.z); Bs[rr][c4 + 3] = f2tf(bv.w);
        }
        __syncthreads();
#pragma unroll
        for (int ks = 0; ks < 2; ks++) {
            int k0 = ks * 8 + (lane & 3);
            uint32_t af[2][4];
#pragma unroll
            for (int im = 0; im < 2; im++) {
                int mr = wm + im * 16 + (lane >> 2);
                af[im][0] = As[mr][k0];     af[im][1] = As[mr + 8][k0];
                af[im][2] = As[mr][k0 + 4]; af[im][3] = As[mr + 8][k0 + 4];
            }
#pragma unroll
            for (int jn = 0; jn < 8; jn++) {
                int nr = wn + jn * 8 + (lane >> 2);
                uint32_t b0 = Bs[nr][k0], b1 = Bs[nr][k0 + 4];
                mma8(acc[0][jn], af[0], b0, b1);
                mma8(acc[1][jn], af[1], b0, b1);
            }
        }
        __syncthreads();
    }

    int cg = 2 * (lane & 3);
#pragma unroll
    for (int im = 0; im < 2; im++) {
#pragma unroll
        for (int half = 0; half < 2; half++) {
            int m = m0 + wm + im * 16 + (lane >> 2) + half * 8;
            if (m >= cnt) continue;
            if (c_idx) {
                int tr = c_idx[m]; float wv = c_w[m];
                float* cp = C + (size_t)tr * ldc + n0 + wn + cg;
#pragma unroll
                for (int jn = 0; jn < 8; jn++) {
                    float2* p = (float2*)(cp + jn * 8);
                    float2 o = *p;
                    o.x += wv * acc[im][jn][half * 2 + 0];
                    o.y += wv * acc[im][jn][half * 2 + 1];
                    *p = o;
                }
            } else {
                float* cp = C + (size_t)m * ldc + n0 + wn + cg;
#pragma unroll
                for (int jn = 0; jn < 8; jn++) {
                    float2 o;
                    o.x = acc[im][jn][half * 2 + 0];
                    o.y = acc[im][jn][half * 2 + 1];
                    *((float2*)(cp + jn * 8)) = o;
                }
            }
        }
    }
}

// ==================== causal attention scores (tf32 MMA) ====================
__global__ void __launch_bounds__(256)
attn_score_mma(const float* __restrict__ Q, const float* __restrict__ Kt) {
    int bh = blockIdx.z, b = bh >> 4, h = bh & 15;
    int m0 = blockIdx.y * 128, n0 = blockIdx.x * 128;
    if (n0 > m0) return;   // fully masked tile: never read by softmax/PV

    const float* Qb = Q + (size_t)b * S_ * H_ + h * HD_;
    const float* Kb = Kt + (size_t)b * S_ * H_ + h * HD_;
    float* Sb = g_att + (size_t)bh * S_ * S_;

    __shared__ uint32_t As[128][20];
    __shared__ uint32_t Bs[128][20];
    int tid = threadIdx.x;
    int lane = tid & 31, w = tid >> 5;
    int wm = (w & 3) * 32, wn = (w >> 2) * 64;
    int r1 = tid >> 2, c4 = (tid & 3) * 4;

    const float* aP[2] = { Qb + (size_t)(m0 + r1) * H_ + c4,
                           Qb + (size_t)(m0 + r1 + 64) * H_ + c4 };
    const float* bP[2] = { Kb + (size_t)(n0 + r1) * H_ + c4,
                           Kb + (size_t)(n0 + r1 + 64) * H_ + c4 };

    float acc[2][8][4];
#pragma unroll
    for (int i = 0; i < 2; i++)
#pragma unroll
        for (int j = 0; j < 8; j++)
#pragma unroll
            for (int q = 0; q < 4; q++) acc[i][j][q] = 0.f;

    for (int kb = 0; kb < HD_; kb += 16) {
#pragma unroll
        for (int h2 = 0; h2 < 2; h2++) {
            float4 av = *(const float4*)(aP[h2] + kb);
            float4 bv = *(const float4*)(bP[h2] + kb);
            int rr = r1 + h2 * 64;
            As[rr][c4 + 0] = f2tf(av.x); As[rr][c4 + 1] = f2tf(av.y);
            As[rr][c4 + 2] = f2tf(av.z); As[rr][c4 + 3] = f2tf(av.w);
            Bs[rr][c4 + 0] = f2tf(bv.x); Bs[rr][c4 + 1] = f2tf(bv.y);
            Bs[rr][c4 + 2] = f2tf(bv.z); Bs[rr][c4 + 3] = f2tf(bv.w);
        }
        __syncthreads();
#pragma unroll
        for (int ks = 0; ks < 2; ks++) {
            int k0 = ks * 8 + (lane & 3);
            uint32_t af[2][4];
#pragma unroll
            for (int im = 0; im < 2; im++) {
                int mr = wm + im * 16 + (lane >> 2);
                af[im][0] = As[mr][k0];     af[im][1] = As[mr + 8][k0];
                af[im][2] = As[mr][k0 + 4]; af[im][3] = As[mr + 8][k0 + 4];
            }
#pragma unroll
            for (int jn = 0; jn < 8; jn++) {
                int nr = wn + jn * 8 + (lane >> 2);
                uint32_t b0 = Bs[nr][k0], b1 = Bs[nr][k0 + 4];
                mma8(acc[0][jn], af[0], b0, b1);
                mma8(acc[1][jn], af[1], b0, b1);
            }
        }
        __syncthreads();
    }

    int cg = 2 * (lane & 3);
#pragma unroll
    for (int im = 0; im < 2; im++) {
#pragma unroll
        for (int half = 0; half < 2; half++) {
            int i = m0 + wm + im * 16 + (lane >> 2) + half * 8;
            float* cp = Sb + (size_t)i * S_ + n0 + wn + cg;
#pragma unroll
            for (int jn = 0; jn < 8; jn++) {
                int j = n0 + wn + cg + jn * 8;
                float2 o;
                o.x = (j     > i) ? -1e30f : acc[im][jn][half * 2 + 0] * ATT_SCALE;
                o.y = (j + 1 > i) ? -1e30f : acc[im][jn][half * 2 + 1] * ATT_SCALE;
                *((float2*)(cp + jn * 8)) = o;
            }
        }
    }
}

// ==================== adaptive row softmax ====================
__global__ void softmax_k() {
    int r = blockIdx.x & (S_ - 1);
    float* row = g_att + (size_t)blockIdx.x * S_;
    int len = r + 1;
    int tid = threadIdx.x;
    float v[8];
    float mx = -1e30f;
#pragma unroll
    for (int i = 0; i < 8; i++) {
        int j = tid + i * 256;
        v[i] = (j < len) ? row[j] : -1e30f;
        mx = fmaxf(mx, v[i]);
    }
    __shared__ float red[32];
    for (int off = 16; off; off >>= 1) mx = fmaxf(mx, __shfl_xor_sync(0xffffffffu, mx, off));
    if ((tid & 31) == 0) red[tid >> 5] = mx;
    __syncthreads();
    if (tid < 32) {
        float m2 = (tid < 8) ? red[tid] : -1e38f;
        for (int off = 16; off; off >>= 1) m2 = fmaxf(m2, __shfl_xor_sync(0xffffffffu, m2, off));
        if (tid == 0) red[0] = m2;
    }
    __syncthreads();
    mx = red[0];
    float s = 0.f;
#pragma unroll
    for (int i = 0; i < 8; i++) { v[i] = __expf(v[i] - mx); s += v[i]; }
    __syncthreads();
    for (int off = 16; off; off >>= 1) s += __shfl_xor_sync(0xffffffffu, s, off);
    if ((tid & 31) == 0) red[tid >> 5] = s;
    __syncthreads();
    if (tid < 32) {
        float s2 = (tid < 8) ? red[tid] : 0.f;
        for (int off = 16; off; off >>= 1) s2 += __shfl_xor_sync(0xffffffffu, s2, off);
        if (tid == 0) red[0] = s2;
    }
    __syncthreads();
    float inv = 1.f / red[0];
#pragma unroll
    for (int i = 0; i < 8; i++) {
        int j = tid + i * 256;
        if (j < len) row[j] = v[i] * inv;
    }
    // zero-fill to the 128-tile boundary so PV's truncated k-loop reads zeros
    int kmax = ((r >> 7) + 1) << 7;
    for (int j = len + tid; j < kmax; j += 256) row[j] = 0.f;
}

// ==================== P @ V (tf32 MMA, causal-truncated) ====================
__global__ void __launch_bounds__(256)
attn_pv_mma(const float* __restrict__ V) {
    int bh = blockIdx.y, b = bh >> 4, h = bh & 15;
    int m0 = blockIdx.x * 128;
    const float* Pb = g_att + (size_t)bh * S_ * S_;
    const float* Vb = V + (size_t)b * S_ * H_ + h * HD_;
    float* Ob = g_ao + (size_t)b * S_ * H_ + h * HD_;

    __shared__ uint32_t As[128][20];
    __shared__ uint32_t Bs[16][136];
    int tid = threadIdx.x;
    int lane = tid & 31, w = tid >> 5;
    int wm = (w & 3) * 32, wn = (w >> 2) * 64;
    int r1 = tid >> 2, c4 = (tid & 3) * 4;
    int kr = tid >> 5, nc4 = (tid & 31) * 4;

    const float* aP[2] = { Pb + (size_t)(m0 + r1) * S_ + c4,
                           Pb + (size_t)(m0 + r1 + 64) * S_ + c4 };

    float acc[2][8][4];
#pragma unroll
    for (int i = 0; i < 2; i++)
#pragma unroll
        for (int j = 0; j < 8; j++)
#pragma unroll
            for (int q = 0; q < 4; q++) acc[i][j][q] = 0.f;

    int kmax = m0 + 128;
    for (int kb = 0; kb < kmax; kb += 16) {
#pragma unroll
        for (int h2 = 0; h2 < 2; h2++) {
            float4 av = *(const float4*)(aP[h2] + kb);
            int rr = r1 + h2 * 64;
            As[rr][c4 + 0] = f2tf(av.x); As[rr][c4 + 1] = f2tf(av.y);
            As[rr][c4 + 2] = f2tf(av.z); As[rr][c4 + 3] = f2tf(av.w);
            float4 bv = *(const float4*)(Vb + (size_t)(kb + kr + h2 * 8) * H_ + nc4);
            int kk = kr + h2 * 8;
            Bs[kk][nc4 + 0] = f2tf(bv.x); Bs[kk][nc4 + 1] = f2tf(bv.y);
            Bs[kk][nc4 + 2] = f2tf(bv.z); Bs[kk][nc4 + 3] = f2tf(bv.w);
        }
        __syncthreads();
#pragma unroll
        for (int ks = 0; ks < 2; ks++) {
            int k0 = ks * 8 + (lane & 3);
            uint32_t af[2][4];
#pragma unroll
            for (int im = 0; im < 2; im++) {
                int mr = wm + im * 16 + (lane >> 2);
                af[im][0] = As[mr][k0];     af[im][1] = As[mr + 8][k0];
                af[im][2] = As[mr][k0 + 4]; af[im][3] = As[mr + 8][k0 + 4];
            }
#pragma unroll
            for (int jn = 0; jn < 8; jn++) {
                int nr = wn + jn * 8 + (lane >> 2);
                uint32_t b0 = Bs[k0][nr], b1 = Bs[k0 + 4][nr];
                mma8(acc[0][jn], af[0], b0, b1);
                mma8(acc[1][jn], af[1], b0, b1);
            }
        }
        __syncthreads();
    }

    int cg = 2 * (lane & 3);
#pragma unroll
    for (int im = 0; im < 2; im++) {
#pragma unroll
        for (int half = 0; half < 2; half++) {
            int m = m0 + wm + im * 16 + (lane >> 2) + half * 8;
            float* cp = Ob + (size_t)m * H_ + wn + cg;
#pragma unroll
            for (int jn = 0; jn < 8; jn++) {
                float2 o;
                o.x = acc[im][jn][half * 2 + 0];
                o.y = acc[im][jn][half * 2 + 1];
                *((float2*)(cp + jn * 8)) = o;
            }
        }
    }
}

// ==================== router ====================
__global__ void router_k(const float* __restrict__ xn2, const float* __restrict__ Wr) {
    int t = blockIdx.x * (blockDim.x >> 5) + (threadIdx.x >> 5);
    if (t >= T_) return;
    int lane = threadIdx.x & 31;
    const float* xr = xn2 + (size_t)t * H_;
    float s[NE_];
#pragma unroll
    for (int e = 0; e < NE_; e++) s[e] = 0.f;
    for (int j = lane; j < H_; j += 32) {
        float xv = xr[j];
#pragma unroll
        for (int e = 0; e < NE_; e++) s[e] += xv * Wr[e * H_ + j];
    }
#pragma unroll
    for (int e = 0; e < NE_; e++)
        for (int off = 16; off; off >>= 1) s[e] += __shfl_xor_sync(0xffffffffu, s[e], off);
    if (lane == 0) {
        int b0 = 0;
#pragma unroll
        for (int e = 1; e < NE_; e++) if (s[e] > s[b0]) b0 = e;
        int b1 = -1;
#pragma unroll
        for (int e = 0; e < NE_; e++) {
            if (e == b0) continue;
            if (b1 < 0 || s[e] > s[b1]) b1 = e;
        }
        float m = s[b0];
        float e0 = __expf(s[b0] - m), e1 = __expf(s[b1] - m);
        float inv = 1.f / (e0 + e1);
        int pos = atomicAdd(&g_cnt[b0], 1);
        g_tok[b0 * T_ + pos] = t; g_wt[b0 * T_ + pos] = e0 * inv;
        pos = atomicAdd(&g_cnt[b1], 1);
        g_tok[b1 * T_ + pos] = t; g_wt[b1 * T_ + pos] = e1 * inv;
    }
}

// ==================== host ====================
extern "C" void kernel_launch(void* const* d_in, const int* in_sizes, int n_in,
                              void* d_out, int out_size) {
    const float* x    = (const float*)d_in[0];
    const float* Wq   = (const float*)d_in[1];
    const float* Wk   = (const float*)d_in[2];
    const float* Wv   = (const float*)d_in[3];
    const float* Wo   = (const float*)d_in[4];
    const float* wln1 = (const float*)d_in[5];
    const float* wln2 = (const float*)d_in[6];
    const float* Wr   = (const float*)d_in[7];
    const float* Wg   = (const float*)d_in[8];
    const float* Wu   = (const float*)d_in[9];
    const float* Wd   = (const float*)d_in[10];
    float* out = (float*)d_out;

    float *p_xn, *p_q, *p_k, *p_v, *p_ao, *p_xn2, *p_hg, *p_hu, *p_wt;
    int *p_tok, *p_cnt;
    cudaGetSymbolAddress((void**)&p_xn,  g_xn);
    cudaGetSymbolAddress((void**)&p_q,   g_q);
    cudaGetSymbolAddress((void**)&p_k,   g_k);
    cudaGetSymbolAddress((void**)&p_v,   g_v);
    cudaGetSymbolAddress((void**)&p_ao,  g_ao);
    cudaGetSymbolAddress((void**)&p_xn2, g_xn2);
    cudaGetSymbolAddress((void**)&p_hg,  g_hg);
    cudaGetSymbolAddress((void**)&p_hu,  g_hu);
    cudaGetSymbolAddress((void**)&p_tok, g_tok);
    cudaGetSymbolAddress((void**)&p_wt,  g_wt);
    cudaGetSymbolAddress((void**)&p_cnt, g_cnt);

    zero_cnt_k<<<1, 32>>>();
    rmsnorm_k<<<T_, 256>>>(x, wln1, p_xn);

    dim3 gProj(H_ / 128, T_ / 128);
    mma_gemm_bt<<<gProj, 256>>>(p_xn, Wq, p_q, T_, H_, H_, H_, H_, H_,
                                nullptr, nullptr, nullptr, nullptr);
    mma_gemm_bt<<<gProj, 256>>>(p_xn, Wk, p_k, T_, H_, H_, H_, H_, H_,
                                nullptr, nullptr, nullptr, nullptr);
    mma_gemm_bt<<<gProj, 256>>>(p_xn, Wv, p_v, T_, H_, H_, H_, H_, H_,
                                nullptr, nullptr, nullptr, nullptr);

    attn_score_mma<<<dim3(S_ / 128, S_ / 128, B_ * NH_), 256>>>(p_q, p_k);
    softmax_k<<<B_ * NH_ * S_, 256>>>();
    attn_pv_mma<<<dim3(S_ / 128, B_ * NH_), 256>>>(p_v);

    mma_gemm_bt<<<gProj, 256>>>(p_ao, Wo, out, T_, H_, H_, H_, H_, H_,
                                nullptr, nullptr, nullptr, nullptr);
    add_residual_k<<<(T_ * H_ / 4 + 255) / 256, 256>>>(out, x);

    rmsnorm_k<<<T_, 256>>>(out, wln2, p_xn2);
    router_k<<<T_ / 8, 256>>>(p_xn2, Wr);

    for (int e = 0; e < NE_; e++) {
        const float* Wge = Wg + (size_t)e * I_ * H_;
        const float* Wue = Wu + (size_t)e * I_ * H_;
        const float* Wde = Wd + (size_t)e * H_ * I_;
        const int*   tok = p_tok + e * T_;
        const float* wte = p_wt + e * T_;
        const int*   cnt = p_cnt + e;
        dim3 gUp(I_ / 128, T_ / 128);
        mma_gemm_bt<<<gUp, 256>>>(p_xn2, Wge, p_hg, T_, I_, H_, H_, H_, I_,
                                  tok, cnt, nullptr, nullptr);
        mma_gemm_bt<<<gUp, 256>>>(p_xn2, Wue, p_hu, T_, I_, H_, H_, H_, I_,
                                  tok, cnt, nullptr, nullptr);
        swiglu2_k<<<2048, 256>>>(p_hg, p_hu, cnt);
        dim3 gDn(H_ / 128, T_ / 128);
        mma_gemm_bt<<<gDn, 256>>>(p_hg, Wde, out, T_, H_, I_, I_, I_, H_,
                                  nullptr, cnt, tok, wte);
    }
}

// round 3
// speedup vs baseline: 5.4976x; 2.0984x over previous
#include <cuda_runtime.h>
#include <math.h>
#include <stdint.h>

#define B_   2
#define S_   2048
#define H_   2048
#define NH_  16
#define HD_  128
#define NE_  8
#define I_   4096
#define T_   (B_*S_)
#define EPS_ 1e-5f
#define ATT_SCALE 0.08838834764831845f

// -------------------- scratch --------------------
__device__ float g_xn [(size_t)T_*H_];
__device__ float g_q  [(size_t)T_*H_];
__device__ float g_k  [(size_t)T_*H_];
__device__ float g_v  [(size_t)T_*H_];
__device__ float g_att[(size_t)B_*NH_*S_*S_];
__device__ float g_ao [(size_t)T_*H_];
__device__ float g_xn2[(size_t)T_*H_];
__device__ float g_hg [(size_t)NE_*T_*I_];
__device__ float g_hu [(size_t)NE_*T_*I_];
__device__ int   g_tok[NE_*T_];
__device__ float g_wt [NE_*T_];
__device__ int   g_cnt[NE_];

// -------------------- helpers --------------------
__device__ __forceinline__ uint32_t f2tf(float f) {
    uint32_t r; asm("cvt.rna.tf32.f32 %0, %1;" : "=r"(r) : "f"(f)); return r;
}
__device__ __forceinline__ void mma8(float* c, const uint32_t* a, uint32_t b0, uint32_t b1) {
    asm volatile("mma.sync.aligned.m16n8k8.row.col.f32.tf32.tf32.f32 "
        "{%0,%1,%2,%3},{%4,%5,%6,%7},{%8,%9},{%0,%1,%2,%3};"
        : "+f"(c[0]), "+f"(c[1]), "+f"(c[2]), "+f"(c[3])
        : "r"(a[0]), "r"(a[1]), "r"(a[2]), "r"(a[3]), "r"(b0), "r"(b1));
}
__device__ __forceinline__ void ldsm4(uint32_t* r, uint32_t addr) {
    asm volatile("ldmatrix.sync.aligned.m8n8.x4.shared.b16 {%0,%1,%2,%3},[%4];"
        : "=r"(r[0]), "=r"(r[1]), "=r"(r[2]), "=r"(r[3]) : "r"(addr));
}
__device__ __forceinline__ void cpa16(uint32_t dst, const void* src) {
    asm volatile("cp.async.cg.shared.global [%0], [%1], 16;" :: "r"(dst), "l"(src));
}
__device__ __forceinline__ void cpa_commit() { asm volatile("cp.async.commit_group;"); }
__device__ __forceinline__ void cpa_wait0()  { asm volatile("cp.async.wait_group 0;"); }
__device__ __forceinline__ uint32_t smem_u32(const void* p) {
    uint32_t a; asm("{ .reg .u64 t; cvta.to.shared.u64 t, %1; cvt.u32.u64 %0, t; }"
                    : "=r"(a) : "l"(p));
    return a;
}

// -------------------- small kernels --------------------
__global__ void zero_cnt_k() { if (threadIdx.x < NE_) g_cnt[threadIdx.x] = 0; }

__global__ void rmsnorm_k(const float* __restrict__ x, const float* __restrict__ w,
                          float* __restrict__ o) {
    int t = blockIdx.x;
    const float* xr = x + (size_t)t * H_;
    float s = 0.f;
    for (int j = threadIdx.x; j < H_; j += blockDim.x) { float v = xr[j]; s += v * v; }
    __shared__ float red[32];
    for (int off = 16; off; off >>= 1) s += __shfl_xor_sync(0xffffffffu, s, off);
    if ((threadIdx.x & 31) == 0) red[threadIdx.x >> 5] = s;
    __syncthreads();
    if (threadIdx.x < 32) {
        float v = (threadIdx.x < (blockDim.x >> 5)) ? red[threadIdx.x] : 0.f;
        for (int off = 16; off; off >>= 1) v += __shfl_xor_sync(0xffffffffu, v, off);
        if (threadIdx.x == 0) red[0] = v;
    }
    __syncthreads();
    float inv = rsqrtf(red[0] / (float)H_ + EPS_);
    float* orow = o + (size_t)t * H_;
    for (int j = threadIdx.x; j < H_; j += blockDim.x) orow[j] = xr[j] * inv * w[j];
}

__global__ void add_residual_k(float* __restrict__ y, const float* __restrict__ x) {
    size_t i = (size_t)blockIdx.x * blockDim.x + threadIdx.x;
    float4* Y = (float4*)y; const float4* X = (const float4*)x;
    if (i < (size_t)T_ * H_ / 4) {
        float4 a = Y[i], b = X[i];
        a.x += b.x; a.y += b.y; a.z += b.z; a.w += b.w;
        Y[i] = a;
    }
}

__global__ void swiglu_all_k(float* __restrict__ hg, const float* __restrict__ hu) {
    int e = blockIdx.y;
    int cnt = g_cnt[e];
    float4* G = (float4*)(hg + (size_t)e * T_ * I_);
    const float4* U = (const float4*)(hu + (size_t)e * T_ * I_);
    size_t total = (size_t)cnt * (I_ / 4);
    size_t stride = (size_t)gridDim.x * blockDim.x;
    for (size_t i = (size_t)blockIdx.x * blockDim.x + threadIdx.x; i < total; i += stride) {
        float4 g = G[i], u = U[i];
        g.x = g.x / (1.f + __expf(-g.x)) * u.x;
        g.y = g.y / (1.f + __expf(-g.y)) * u.y;
        g.z = g.z / (1.f + __expf(-g.z)) * u.z;
        g.w = g.w / (1.f + __expf(-g.w)) * u.w;
        G[i] = g;
    }
}

// ==================== tf32 MMA GEMM (ldmatrix + cp.async, double-buffered) ====================
// C[M,N] = A[M,K] * B[N,K]^T.  Mode 0: z picks (B,C) triple (QKV / Wo).
// Mode 1: z = expert*2+{gate,up}; rows of A gathered via token list; dense store.
// Mode 2: z = expert; dense A (per-expert hg); scatter-add (atomic) epilogue.
struct GArgs {
    const float* A;
    const float* B0; const float* B1; const float* B2;
    float* C0; float* C1; float* C2;
    int M, N, K, lda, ldb, ldc;
    const int* tok; const float* wt; const int* cntp;
    size_t aStride, bStride, cStride;
    int mode;
};

#define BK 32
#define SROW 36                       // words per smem row (pad: 36 mod 32 = 4 -> conflict-free)
#define SOFF (128*SROW*4)             // stage size in bytes
#define SMEM_BYTES (4*SOFF)           // A(2 stages) + B(2 stages)

__global__ void __launch_bounds__(256, 2)
mma_gemm2(const GArgs args) {
    int z = blockIdx.z;
    const float* A = args.A;
    const float* B;
    float* C;
    const int* a_idx = nullptr; const int* c_idx = nullptr; const float* c_w = nullptr;
    int cnt = args.M;
    bool atomic_ep = false;

    if (args.mode == 0) {
        B = (z == 0) ? args.B0 : (z == 1 ? args.B1 : args.B2);
        C = (z == 0) ? args.C0 : (z == 1 ? args.C1 : args.C2);
    } else if (args.mode == 1) {
        int e = z >> 1;
        B = ((z & 1) ? args.B1 : args.B0) + (size_t)e * args.bStride;
        C = ((z & 1) ? args.C1 : args.C0) + (size_t)e * args.cStride;
        a_idx = args.tok + e * T_;
        cnt = args.cntp[e];
    } else {
        int e = z;
        A = args.A + (size_t)e * args.aStride;
        B = args.B0 + (size_t)e * args.bStride;
        C = args.C0;
        c_idx = args.tok + e * T_;
        c_w = args.wt + e * T_;
        cnt = args.cntp[e];
        atomic_ep = true;
    }

    int m0 = blockIdx.y * 128, n0 = blockIdx.x * 128;
    if (m0 >= cnt) return;

    extern __shared__ float sm[];
    uint32_t sA = smem_u32(sm);
    uint32_t sB = sA + 2 * SOFF;

    int tid = threadIdx.x;
    int lane = tid & 31, w = tid >> 5;
    int wm = (w & 3) * 32, wn = (w >> 2) * 64;

    // ---- loader setup: 256 threads, each 4 rows x 16B per matrix per stage ----
    int lrow = tid >> 3;           // 0..31
    int lcol = (tid & 7) * 4;      // word 0..28
    const float* gA[4]; const float* gB[4];
    uint32_t stA[4], stB[4];
#pragma unroll
    for (int rr = 0; rr < 4; rr++) {
        int mr = m0 + lrow + rr * 32;
        int grow;
        if (a_idx) grow = (mr < cnt) ? a_idx[mr] : 0;
        else       grow = mr;
        gA[rr] = A + (size_t)grow * args.lda + lcol;
        gB[rr] = B + (size_t)(n0 + lrow + rr * 32) * args.ldb + lcol;
        stA[rr] = sA + ((lrow + rr * 32) * SROW + lcol) * 4;
        stB[rr] = sB + ((lrow + rr * 32) * SROW + lcol) * 4;
    }

    // ---- ldmatrix addresses ----
    uint32_t aAddr = sA + ((wm + (lane & 15)) * SROW + 4 * ((lane >> 4) & 1)) * 4;
    uint32_t bAddr = sB + ((wn + (lane & 7) + 8 * ((lane >> 4) & 1)) * SROW
                           + 4 * ((lane >> 3) & 1)) * 4;

    float acc[2][8][4];
#pragma unroll
    for (int i = 0; i < 2; i++)
#pragma unroll
        for (int j = 0; j < 8; j++)
#pragma unroll
            for (int q = 0; q < 4; q++) acc[i][j][q] = 0.f;

    int nk = args.K / BK;

    // prefetch stage 0
#pragma unroll
    for (int rr = 0; rr < 4; rr++) { cpa16(stA[rr], gA[rr]); cpa16(stB[rr], gB[rr]); }
    cpa_commit();

    for (int kt = 0; kt < nk; kt++) {
        cpa_wait0();
        __syncthreads();
        if (kt + 1 < nk) {
            int kb = (kt + 1) * BK;
            uint32_t off = ((kt + 1) & 1) * SOFF;
#pragma unroll
            for (int rr = 0; rr < 4; rr++) {
                cpa16(stA[rr] + off, gA[rr] + kb);
                cpa16(stB[rr] + off, gB[rr] + kb);
            }
        }
        cpa_commit();

        uint32_t soff = (kt & 1) * SOFF;
#pragma unroll
        for (int ks = 0; ks < 4; ks++) {
            uint32_t koff = soff + ks * 32;
            uint32_t a[2][4];
            ldsm4(a[0], aAddr + koff);
            ldsm4(a[1], aAddr + koff + 16 * SROW * 4);
            uint32_t b[4][4];
#pragma unroll
            for (int jp = 0; jp < 4; jp++)
                ldsm4(b[jp], bAddr + koff + jp * (16 * SROW * 4));
#pragma unroll
            for (int im = 0; im < 2; im++)
#pragma unroll
                for (int jn = 0; jn < 8; jn++)
                    mma8(acc[im][jn], a[im], b[jn >> 1][(jn & 1) * 2], b[jn >> 1][(jn & 1) * 2 + 1]);
        }
        __syncthreads();
    }

    int cg = 2 * (lane & 3);
#pragma unroll
    for (int im = 0; im < 2; im++) {
#pragma unroll
        for (int half = 0; half < 2; half++) {
            int m = m0 + wm + im * 16 + (lane >> 2) + half * 8;
            if (m >= cnt) continue;
            if (atomic_ep) {
                int tr = c_idx[m]; float wv = c_w[m];
                float* cp = C + (size_t)tr * args.ldc + n0 + wn + cg;
#pragma unroll
                for (int jn = 0; jn < 8; jn++) {
                    atomicAdd(cp + jn * 8,     wv * acc[im][jn][half * 2 + 0]);
                    atomicAdd(cp + jn * 8 + 1, wv * acc[im][jn][half * 2 + 1]);
                }
            } else {
                float* cp = C + (size_t)m * args.ldc + n0 + wn + cg;
#pragma unroll
                for (int jn = 0; jn < 8; jn++) {
                    float2 o;
                    o.x = acc[im][jn][half * 2 + 0];
                    o.y = acc[im][jn][half * 2 + 1];
                    *((float2*)(cp + jn * 8)) = o;
                }
            }
        }
    }
}

// ==================== causal attention scores (tf32 MMA) ====================
__global__ void __launch_bounds__(256)
attn_score_mma(const float* __restrict__ Q, const float* __restrict__ Kt) {
    int bh = blockIdx.z, b = bh >> 4, h = bh & 15;
    int m0 = blockIdx.y * 128, n0 = blockIdx.x * 128;
    if (n0 > m0) return;

    const float* Qb = Q + (size_t)b * S_ * H_ + h * HD_;
    const float* Kb = Kt + (size_t)b * S_ * H_ + h * HD_;
    float* Sb = g_att + (size_t)bh * S_ * S_;

    __shared__ uint32_t As[128][20];
    __shared__ uint32_t Bs[128][20];
    int tid = threadIdx.x;
    int lane = tid & 31, w = tid >> 5;
    int wm = (w & 3) * 32, wn = (w >> 2) * 64;
    int r1 = tid >> 2, c4 = (tid & 3) * 4;

    const float* aP[2] = { Qb + (size_t)(m0 + r1) * H_ + c4,
                           Qb + (size_t)(m0 + r1 + 64) * H_ + c4 };
    const float* bP[2] = { Kb + (size_t)(n0 + r1) * H_ + c4,
                           Kb + (size_t)(n0 + r1 + 64) * H_ + c4 };

    float acc[2][8][4];
#pragma unroll
    for (int i = 0; i < 2; i++)
#pragma unroll
        for (int j = 0; j < 8; j++)
#pragma unroll
            for (int q = 0; q < 4; q++) acc[i][j][q] = 0.f;

    for (int kb = 0; kb < HD_; kb += 16) {
#pragma unroll
        for (int h2 = 0; h2 < 2; h2++) {
            float4 av = *(const float4*)(aP[h2] + kb);
            float4 bv = *(const float4*)(bP[h2] + kb);
            int rr = r1 + h2 * 64;
            As[rr][c4 + 0] = f2tf(av.x); As[rr][c4 + 1] = f2tf(av.y);
            As[rr][c4 + 2] = f2tf(av.z); As[rr][c4 + 3] = f2tf(av.w);
            Bs[rr][c4 + 0] = f2tf(bv.x); Bs[rr][c4 + 1] = f2tf(bv.y);
            Bs[rr][c4 + 2] = f2tf(bv.z); Bs[rr][c4 + 3] = f2tf(bv.w);
        }
        __syncthreads();
#pragma unroll
        for (int ks = 0; ks < 2; ks++) {
            int k0 = ks * 8 + (lane & 3);
            uint32_t af[2][4];
#pragma unroll
            for (int im = 0; im < 2; im++) {
                int mr = wm + im * 16 + (lane >> 2);
                af[im][0] = As[mr][k0];     af[im][1] = As[mr + 8][k0];
                af[im][2] = As[mr][k0 + 4]; af[im][3] = As[mr + 8][k0 + 4];
            }
#pragma unroll
            for (int jn = 0; jn < 8; jn++) {
                int nr = wn + jn * 8 + (lane >> 2);
                uint32_t b0 = Bs[nr][k0], b1 = Bs[nr][k0 + 4];
                mma8(acc[0][jn], af[0], b0, b1);
                mma8(acc[1][jn], af[1], b0, b1);
            }
        }
        __syncthreads();
    }

    int cg = 2 * (lane & 3);
#pragma unroll
    for (int im = 0; im < 2; im++) {
#pragma unroll
        for (int half = 0; half < 2; half++) {
            int i = m0 + wm + im * 16 + (lane >> 2) + half * 8;
            float* cp = Sb + (size_t)i * S_ + n0 + wn + cg;
#pragma unroll
            for (int jn = 0; jn < 8; jn++) {
                int j = n0 + wn + cg + jn * 8;
                float2 o;
                o.x = (j     > i) ? -1e30f : acc[im][jn][half * 2 + 0] * ATT_SCALE;
                o.y = (j + 1 > i) ? -1e30f : acc[im][jn][half * 2 + 1] * ATT_SCALE;
                *((float2*)(cp + jn * 8)) = o;
            }
        }
    }
}

// ==================== adaptive row softmax ====================
__global__ void softmax_k() {
    int r = blockIdx.x & (S_ - 1);
    float* row = g_att + (size_t)blockIdx.x * S_;
    int len = r + 1;
    int tid = threadIdx.x;
    float v[8];
    float mx = -1e30f;
#pragma unroll
    for (int i = 0; i < 8; i++) {
        int j = tid + i * 256;
        v[i] = (j < len) ? row[j] : -1e30f;
        mx = fmaxf(mx, v[i]);
    }
    __shared__ float red[32];
    for (int off = 16; off; off >>= 1) mx = fmaxf(mx, __shfl_xor_sync(0xffffffffu, mx, off));
    if ((tid & 31) == 0) red[tid >> 5] = mx;
    __syncthreads();
    if (tid < 32) {
        float m2 = (tid < 8) ? red[tid] : -1e38f;
        for (int off = 16; off; off >>= 1) m2 = fmaxf(m2, __shfl_xor_sync(0xffffffffu, m2, off));
        if (tid == 0) red[0] = m2;
    }
    __syncthreads();
    mx = red[0];
    float s = 0.f;
#pragma unroll
    for (int i = 0; i < 8; i++) { v[i] = __expf(v[i] - mx); s += v[i]; }
    __syncthreads();
    for (int off = 16; off; off >>= 1) s += __shfl_xor_sync(0xffffffffu, s, off);
    if ((tid & 31) == 0) red[tid >> 5] = s;
    __syncthreads();
    if (tid < 32) {
        float s2 = (tid < 8) ? red[tid] : 0.f;
        for (int off = 16; off; off >>= 1) s2 += __shfl_xor_sync(0xffffffffu, s2, off);
        if (tid == 0) red[0] = s2;
    }
    __syncthreads();
    float inv = 1.f / red[0];
#pragma unroll
    for (int i = 0; i < 8; i++) {
        int j = tid + i * 256;
        if (j < len) row[j] = v[i] * inv;
    }
    int kmax = ((r >> 7) + 1) << 7;
    for (int j = len + tid; j < kmax; j += 256) row[j] = 0.f;
}

// ==================== P @ V (tf32 MMA, causal-truncated) ====================
__global__ void __launch_bounds__(256)
attn_pv_mma(const float* __restrict__ V) {
    int bh = blockIdx.y, b = bh >> 4, h = bh & 15;
    int m0 = blockIdx.x * 128;
    const float* Pb = g_att + (size_t)bh * S_ * S_;
    const float* Vb = V + (size_t)b * S_ * H_ + h * HD_;
    float* Ob = g_ao + (size_t)b * S_ * H_ + h * HD_;

    __shared__ uint32_t As[128][20];
    __shared__ uint32_t Bs[16][136];
    int tid = threadIdx.x;
    int lane = tid & 31, w = tid >> 5;
    int wm = (w & 3) * 32, wn = (w >> 2) * 64;
    int r1 = tid >> 2, c4 = (tid & 3) * 4;
    int kr = tid >> 5, nc4 = (tid & 31) * 4;

    const float* aP[2] = { Pb + (size_t)(m0 + r1) * S_ + c4,
                           Pb + (size_t)(m0 + r1 + 64) * S_ + c4 };

    float acc[2][8][4];
#pragma unroll
    for (int i = 0; i < 2; i++)
#pragma unroll
        for (int j = 0; j < 8; j++)
#pragma unroll
            for (int q = 0; q < 4; q++) acc[i][j][q] = 0.f;

    int kmax = m0 + 128;
    for (int kb = 0; kb < kmax; kb += 16) {
#pragma unroll
        for (int h2 = 0; h2 < 2; h2++) {
            float4 av = *(const float4*)(aP[h2] + kb);
            int rr = r1 + h2 * 64;
            As[rr][c4 + 0] = f2tf(av.x); As[rr][c4 + 1] = f2tf(av.y);
            As[rr][c4 + 2] = f2tf(av.z); As[rr][c4 + 3] = f2tf(av.w);
            float4 bv = *(const float4*)(Vb + (size_t)(kb + kr + h2 * 8) * H_ + nc4);
            int kk = kr + h2 * 8;
            Bs[kk][nc4 + 0] = f2tf(bv.x); Bs[kk][nc4 + 1] = f2tf(bv.y);
            Bs[kk][nc4 + 2] = f2tf(bv.z); Bs[kk][nc4 + 3] = f2tf(bv.w);
        }
        __syncthreads();
#pragma unroll
        for (int ks = 0; ks < 2; ks++) {
            int k0 = ks * 8 + (lane & 3);
            uint32_t af[2][4];
#pragma unroll
            for (int im = 0; im < 2; im++) {
                int mr = wm + im * 16 + (lane >> 2);
                af[im][0] = As[mr][k0];     af[im][1] = As[mr + 8][k0];
                af[im][2] = As[mr][k0 + 4]; af[im][3] = As[mr + 8][k0 + 4];
            }
#pragma unroll
            for (int jn = 0; jn < 8; jn++) {
                int nr = wn + jn * 8 + (lane >> 2);
                uint32_t b0 = Bs[k0][nr], b1 = Bs[k0 + 4][nr];
                mma8(acc[0][jn], af[0], b0, b1);
                mma8(acc[1][jn], af[1], b0, b1);
            }
        }
        __syncthreads();
    }

    int cg = 2 * (lane & 3);
#pragma unroll
    for (int im = 0; im < 2; im++) {
#pragma unroll
        for (int half = 0; half < 2; half++) {
            int m = m0 + wm + im * 16 + (lane >> 2) + half * 8;
            float* cp = Ob + (size_t)m * H_ + wn + cg;
#pragma unroll
            for (int jn = 0; jn < 8; jn++) {
                float2 o;
                o.x = acc[im][jn][half * 2 + 0];
                o.y = acc[im][jn][half * 2 + 1];
                *((float2*)(cp + jn * 8)) = o;
            }
        }
    }
}

// ==================== router ====================
__global__ void router_k(const float* __restrict__ xn2, const float* __restrict__ Wr) {
    int t = blockIdx.x * (blockDim.x >> 5) + (threadIdx.x >> 5);
    if (t >= T_) return;
    int lane = threadIdx.x & 31;
    const float* xr = xn2 + (size_t)t * H_;
    float s[NE_];
#pragma unroll
    for (int e = 0; e < NE_; e++) s[e] = 0.f;
    for (int j = lane; j < H_; j += 32) {
        float xv = xr[j];
#pragma unroll
        for (int e = 0; e < NE_; e++) s[e] += xv * Wr[e * H_ + j];
    }
#pragma unroll
    for (int e = 0; e < NE_; e++)
        for (int off = 16; off; off >>= 1) s[e] += __shfl_xor_sync(0xffffffffu, s[e], off);
    if (lane == 0) {
        int b0 = 0;
#pragma unroll
        for (int e = 1; e < NE_; e++) if (s[e] > s[b0]) b0 = e;
        int b1 = -1;
#pragma unroll
        for (int e = 0; e < NE_; e++) {
            if (e == b0) continue;
            if (b1 < 0 || s[e] > s[b1]) b1 = e;
        }
        float m = s[b0];
        float e0 = __expf(s[b0] - m), e1 = __expf(s[b1] - m);
        float inv = 1.f / (e0 + e1);
        int pos = atomicAdd(&g_cnt[b0], 1);
        g_tok[b0 * T_ + pos] = t; g_wt[b0 * T_ + pos] = e0 * inv;
        pos = atomicAdd(&g_cnt[b1], 1);
        g_tok[b1 * T_ + pos] = t; g_wt[b1 * T_ + pos] = e1 * inv;
    }
}

// ==================== host ====================
extern "C" void kernel_launch(void* const* d_in, const int* in_sizes, int n_in,
                              void* d_out, int out_size) {
    const float* x    = (const float*)d_in[0];
    const float* Wq   = (const float*)d_in[1];
    const float* Wk   = (const float*)d_in[2];
    const float* Wv   = (const float*)d_in[3];
    const float* Wo   = (const float*)d_in[4];
    const float* wln1 = (const float*)d_in[5];
    const float* wln2 = (const float*)d_in[6];
    const float* Wr   = (const float*)d_in[7];
    const float* Wg   = (const float*)d_in[8];
    const float* Wu   = (const float*)d_in[9];
    const float* Wd   = (const float*)d_in[10];
    float* out = (float*)d_out;

    float *p_xn, *p_q, *p_k, *p_v, *p_ao, *p_xn2, *p_hg, *p_hu, *p_wt;
    int *p_tok, *p_cnt;
    cudaGetSymbolAddress((void**)&p_xn,  g_xn);
    cudaGetSymbolAddress((void**)&p_q,   g_q);
    cudaGetSymbolAddress((void**)&p_k,   g_k);
    cudaGetSymbolAddress((void**)&p_v,   g_v);
    cudaGetSymbolAddress((void**)&p_ao,  g_ao);
    cudaGetSymbolAddress((void**)&p_xn2, g_xn2);
    cudaGetSymbolAddress((void**)&p_hg,  g_hg);
    cudaGetSymbolAddress((void**)&p_hu,  g_hu);
    cudaGetSymbolAddress((void**)&p_tok, g_tok);
    cudaGetSymbolAddress((void**)&p_wt,  g_wt);
    cudaGetSymbolAddress((void**)&p_cnt, g_cnt);

    static int smem_set = 0;
    if (!smem_set) {
        cudaFuncSetAttribute(mma_gemm2, cudaFuncAttributeMaxDynamicSharedMemorySize, SMEM_BYTES);
        smem_set = 1;
    }

    zero_cnt_k<<<1, 32>>>();
    rmsnorm_k<<<T_, 256>>>(x, wln1, p_xn);

    // QKV fused launch (z = 0,1,2)
    {
        GArgs a = {};
        a.A = p_xn; a.B0 = Wq; a.B1 = Wk; a.B2 = Wv;
        a.C0 = p_q; a.C1 = p_k; a.C2 = p_v;
        a.M = T_; a.N = H_; a.K = H_; a.lda = H_; a.ldb = H_; a.ldc = H_;
        a.mode = 0;
        mma_gemm2<<<dim3(H_ / 128, T_ / 128, 3), 256, SMEM_BYTES>>>(a);
    }

    attn_score_mma<<<dim3(S_ / 128, S_ / 128, B_ * NH_), 256>>>(p_q, p_k);
    softmax_k<<<B_ * NH_ * S_, 256>>>();
    attn_pv_mma<<<dim3(S_ / 128, B_ * NH_), 256>>>(p_v);

    // Wo projection
    {
        GArgs a = {};
        a.A = p_ao; a.B0 = Wo; a.C0 = out;
        a.M = T_; a.N = H_; a.K = H_; a.lda = H_; a.ldb = H_; a.ldc = H_;
        a.mode = 0;
        mma_gemm2<<<dim3(H_ / 128, T_ / 128, 1), 256, SMEM_BYTES>>>(a);
    }
    add_residual_k<<<(T_ * H_ / 4 + 255) / 256, 256>>>(out, x);

    rmsnorm_k<<<T_, 256>>>(out, wln2, p_xn2);
    router_k<<<T_ / 8, 256>>>(p_xn2, Wr);

    // MoE gate+up: one launch, z = expert*2 + {gate,up}
    {
        GArgs a = {};
        a.A = p_xn2; a.B0 = Wg; a.B1 = Wu;
        a.C0 = p_hg; a.C1 = p_hu;
        a.M = T_; a.N = I_; a.K = H_; a.lda = H_; a.ldb = H_; a.ldc = I_;
        a.tok = p_tok; a.cntp = p_cnt;
        a.bStride = (size_t)I_ * H_; a.cStride = (size_t)T_ * I_;
        a.mode = 1;
        mma_gemm2<<<dim3(I_ / 128, T_ / 128, 2 * NE_), 256, SMEM_BYTES>>>(a);
    }

    swiglu_all_k<<<dim3(512, NE_), 256>>>(p_hg, p_hu);

    // MoE down: one launch, z = expert, atomic scatter-add into out
    {
        GArgs a = {};
        a.A = p_hg; a.B0 = Wd; a.C0 = out;
        a.M = T_; a.N = H_; a.K = I_; a.lda = I_; a.ldb = I_; a.ldc = H_;
        a.tok = p_tok; a.wt = p_wt; a.cntp = p_cnt;
        a.aStride = (size_t)T_ * I_; a.bStride = (size_t)H_ * I_;
        a.mode = 2;
        mma_gemm2<<<dim3(H_ / 128, T_ / 128, NE_), 256, SMEM_BYTES>>>(a);
    }
}